// round 1
// baseline (speedup 1.0000x reference)
#include <cuda_runtime.h>
#include <math.h>

// Problem dims (fixed by the dataset)
#define NMAX   80000
#define N1MAX  40000
#define N2MAX  20000
#define NUMK   27
#define BGRAPH 16

// ---------------- scratch (static __device__ — no allocations) ----------------
__device__ float d_xw1[NMAX  * NUMK * 8];    // 69 MB
__device__ float d_xw2[N1MAX * NUMK * 16];   // 69 MB
__device__ float d_agg1[NMAX * 8];
__device__ int   d_cnt1[NMAX];
__device__ float d_x1max[N1MAX * 8];
__device__ int   d_batch1[N1MAX];
__device__ float d_agg2[N1MAX * 16];
__device__ int   d_cnt2[N1MAX];
__device__ float d_x2max[N2MAX * 16];
__device__ int   d_batch2[N2MAX];
__device__ float d_gsum[BGRAPH * 16];
__device__ int   d_gcnt[BGRAPH];

// ---------------- helpers ----------------
__device__ __forceinline__ float elu1(float v) {
    return v > 0.0f ? v : (expf(v) - 1.0f);
}

// float atomic max via signed/unsigned int ordering trick (correct for mixed signs)
__device__ __forceinline__ void atomicMaxFloat(float* addr, float value) {
    if (value >= 0.0f)
        atomicMax((int*)addr, __float_as_int(value));
    else
        atomicMin((unsigned int*)addr, __float_as_uint(value));
}

// vectorized global reduction (sm_90+): 1 instruction, 4 floats
__device__ __forceinline__ void red_add_v4(float* p, float4 v) {
    asm volatile("red.global.add.v4.f32 [%0], {%1,%2,%3,%4};"
                 :: "l"(p), "f"(v.x), "f"(v.y), "f"(v.z), "f"(v.w) : "memory");
}

// degree-1 open B-spline basis on 3-dim pseudo coords, K=3
__device__ __forceinline__ void basis27(float a0, float a1, float a2,
                                        float* bw, int* kk) {
    float v0 = a0 * 2.0f, v1 = a1 * 2.0f, v2 = a2 * 2.0f;
    int i0 = (int)v0; i0 = i0 < 0 ? 0 : (i0 > 1 ? 1 : i0);
    int i1 = (int)v1; i1 = i1 < 0 ? 0 : (i1 > 1 ? 1 : i1);
    int i2 = (int)v2; i2 = i2 < 0 ? 0 : (i2 > 1 ? 1 : i2);
    float f0 = v0 - (float)i0, f1 = v1 - (float)i1, f2 = v2 - (float)i2;
    float g0 = 1.0f - f0, g1 = 1.0f - f1, g2 = 1.0f - f2;
#pragma unroll
    for (int s = 0; s < 8; s++) {
        int b0 = s & 1, b1 = (s >> 1) & 1, b2 = (s >> 2) & 1;
        float w0 = b0 ? f0 : g0;
        float w1 = b1 ? f1 : g1;
        float w2 = b2 ? f2 : g2;
        bw[s] = w0 * w1 * w2;
        kk[s] = (i0 + b0) + 3 * (i1 + b1) + 9 * (i2 + b2);
    }
}

// ---------------- kernels ----------------

__global__ void k_init(int N, int N1, int N2) {
    int tid = blockIdx.x * blockDim.x + threadIdx.x;
    int stride = gridDim.x * blockDim.x;
    for (int i = tid; i < N * 8; i += stride)  d_agg1[i] = 0.0f;
    for (int i = tid; i < N; i += stride)      d_cnt1[i] = 0;
    for (int i = tid; i < N1 * 8; i += stride) d_x1max[i] = -INFINITY;
    for (int i = tid; i < N1; i += stride)     d_batch1[i] = -0x7fffffff - 1;
    for (int i = tid; i < N1 * 16; i += stride) d_agg2[i] = 0.0f;
    for (int i = tid; i < N1; i += stride)     d_cnt2[i] = 0;
    for (int i = tid; i < N2 * 16; i += stride) d_x2max[i] = -INFINITY;
    for (int i = tid; i < N2; i += stride)     d_batch2[i] = -0x7fffffff - 1;
    for (int i = tid; i < BGRAPH * 16; i += stride) d_gsum[i] = 0.0f;
    for (int i = tid; i < BGRAPH; i += stride) d_gcnt[i] = 0;
}

// xW1[n][k][o] = x[n] @ W1[k]   (N*27 threads, 8 outputs each)
__global__ void k_xw1(const float* __restrict__ x, const float* __restrict__ W1, int N) {
    int idx = blockIdx.x * blockDim.x + threadIdx.x;
    if (idx >= N * NUMK) return;
    int n = idx / NUMK;
    int k = idx - n * NUMK;
    float x0 = x[2 * n], x1 = x[2 * n + 1];
    const float* w = W1 + k * 16;
    float4 r0, r1;
    r0.x = x0 * w[0] + x1 * w[8];
    r0.y = x0 * w[1] + x1 * w[9];
    r0.z = x0 * w[2] + x1 * w[10];
    r0.w = x0 * w[3] + x1 * w[11];
    r1.x = x0 * w[4] + x1 * w[12];
    r1.y = x0 * w[5] + x1 * w[13];
    r1.z = x0 * w[6] + x1 * w[14];
    r1.w = x0 * w[7] + x1 * w[15];
    float4* out = (float4*)(d_xw1) + (size_t)idx * 2;
    out[0] = r0;
    out[1] = r1;
}

// level-1 edge kernel: gather 8 corners of xW1, weight by basis, scatter-add to dst
__global__ void k_edge1(const int* __restrict__ ei, const float* __restrict__ attr, int E) {
    int e = blockIdx.x * blockDim.x + threadIdx.x;
    if (e >= E) return;
    int src = ei[e];
    int dst = ei[E + e];
    float a0 = attr[3 * e], a1 = attr[3 * e + 1], a2 = attr[3 * e + 2];
    float bw[8]; int kk[8];
    basis27(a0, a1, a2, bw, kk);
    const float4* base = (const float4*)(d_xw1 + (size_t)src * (NUMK * 8));
    float4 m0 = make_float4(0, 0, 0, 0), m1 = make_float4(0, 0, 0, 0);
#pragma unroll
    for (int s = 0; s < 8; s++) {
        const float4* p = base + kk[s] * 2;
        float4 w0 = __ldg(p);
        float4 w1 = __ldg(p + 1);
        float b = bw[s];
        m0.x += b * w0.x; m0.y += b * w0.y; m0.z += b * w0.z; m0.w += b * w0.w;
        m1.x += b * w1.x; m1.y += b * w1.y; m1.z += b * w1.z; m1.w += b * w1.w;
    }
    float* out = d_agg1 + (size_t)dst * 8;
    red_add_v4(out, m0);
    red_add_v4(out + 4, m1);
    atomicAdd(&d_cnt1[dst], 1);
}

// level-1 node kernel: mean + root + bias + ELU, then seg_max pooling scatter
__global__ void k_node1(const float* __restrict__ x, const int* __restrict__ batch,
                        const int* __restrict__ cluster1,
                        const float* __restrict__ root1, const float* __restrict__ b1,
                        int N) {
    int n = blockIdx.x * blockDim.x + threadIdx.x;
    if (n >= N) return;
    int c = d_cnt1[n];
    float inv = 1.0f / (float)(c > 1 ? c : 1);
    float x0 = x[2 * n], x1 = x[2 * n + 1];
    int c1 = cluster1[n];
    int bt = batch[n];
    float* xm = d_x1max + (size_t)c1 * 8;
#pragma unroll
    for (int o = 0; o < 8; o++) {
        float h = d_agg1[(size_t)n * 8 + o] * inv + x0 * root1[o] + x1 * root1[8 + o] + b1[o];
        h = elu1(h);
        atomicMaxFloat(&xm[o], h);
    }
    atomicMax(&d_batch1[c1], bt);
}

// xW2[n1][k][o] = x1_fixed[n1] @ W2[k]   (N1*27 threads, 16 outputs each)
__global__ void k_xw2(const float* __restrict__ W2, int N1) {
    int idx = blockIdx.x * blockDim.x + threadIdx.x;
    if (idx >= N1 * NUMK) return;
    int n = idx / NUMK;
    int k = idx - n * NUMK;
    float xv[8];
#pragma unroll
    for (int c = 0; c < 8; c++) {
        float t = d_x1max[(size_t)n * 8 + c];
        xv[c] = (t == -INFINITY) ? 0.0f : t;   // seg_max empty-cluster fix
    }
    const float* w = W2 + k * 128;
    float r[16];
#pragma unroll
    for (int o = 0; o < 16; o++) r[o] = 0.0f;
#pragma unroll
    for (int c = 0; c < 8; c++) {
        float xc = xv[c];
        const float* wr = w + c * 16;
#pragma unroll
        for (int o = 0; o < 16; o++) r[o] += xc * wr[o];
    }
    float4* out = (float4*)(d_xw2) + (size_t)idx * 4;
    out[0] = make_float4(r[0], r[1], r[2], r[3]);
    out[1] = make_float4(r[4], r[5], r[6], r[7]);
    out[2] = make_float4(r[8], r[9], r[10], r[11]);
    out[3] = make_float4(r[12], r[13], r[14], r[15]);
}

// level-2 edge kernel on coarsened graph
__global__ void k_edge2(const int* __restrict__ ei, const float* __restrict__ attr,
                        const int* __restrict__ cluster1, int E) {
    int e = blockIdx.x * blockDim.x + threadIdx.x;
    if (e >= E) return;
    int src = ei[e];
    int dst = ei[E + e];
    int s2 = cluster1[src];
    int d2 = cluster1[dst];
    float a0 = attr[3 * e], a1 = attr[3 * e + 1], a2 = attr[3 * e + 2];
    float bw[8]; int kk[8];
    basis27(a0, a1, a2, bw, kk);
    const float4* base = (const float4*)(d_xw2 + (size_t)s2 * (NUMK * 16));
    float4 m0 = make_float4(0, 0, 0, 0), m1 = m0, m2 = m0, m3 = m0;
#pragma unroll
    for (int s = 0; s < 8; s++) {
        const float4* p = base + kk[s] * 4;
        float4 w0 = __ldg(p);
        float4 w1 = __ldg(p + 1);
        float4 w2 = __ldg(p + 2);
        float4 w3 = __ldg(p + 3);
        float b = bw[s];
        m0.x += b * w0.x; m0.y += b * w0.y; m0.z += b * w0.z; m0.w += b * w0.w;
        m1.x += b * w1.x; m1.y += b * w1.y; m1.z += b * w1.z; m1.w += b * w1.w;
        m2.x += b * w2.x; m2.y += b * w2.y; m2.z += b * w2.z; m2.w += b * w2.w;
        m3.x += b * w3.x; m3.y += b * w3.y; m3.z += b * w3.z; m3.w += b * w3.w;
    }
    float* out = d_agg2 + (size_t)d2 * 16;
    red_add_v4(out, m0);
    red_add_v4(out + 4, m1);
    red_add_v4(out + 8, m2);
    red_add_v4(out + 12, m3);
    atomicAdd(&d_cnt2[d2], 1);
}

// level-2 node kernel: mean + root + bias + ELU, then seg_max pooling scatter
__global__ void k_node2(const int* __restrict__ cluster2,
                        const float* __restrict__ root2, const float* __restrict__ b2,
                        int N1) {
    int n = blockIdx.x * blockDim.x + threadIdx.x;
    if (n >= N1) return;
    int c = d_cnt2[n];
    float inv = 1.0f / (float)(c > 1 ? c : 1);
    float xv[8];
#pragma unroll
    for (int i = 0; i < 8; i++) {
        float t = d_x1max[(size_t)n * 8 + i];
        xv[i] = (t == -INFINITY) ? 0.0f : t;
    }
    int c2 = cluster2[n];
    int b1v = d_batch1[n];
    int bt = b1v > 0 ? b1v : 0;
    float* xm = d_x2max + (size_t)c2 * 16;
#pragma unroll
    for (int o = 0; o < 16; o++) {
        float r = 0.0f;
#pragma unroll
        for (int i = 0; i < 8; i++) r += xv[i] * root2[i * 16 + o];
        float h = d_agg2[(size_t)n * 16 + o] * inv + r + b2[o];
        h = elu1(h);
        atomicMaxFloat(&xm[o], h);
    }
    atomicMax(&d_batch2[c2], bt);
}

// scatter_mean over graphs
__global__ void k_final(int N2) {
    int n = blockIdx.x * blockDim.x + threadIdx.x;
    if (n >= N2) return;
    int b2v = d_batch2[n];
    int b = b2v > 0 ? b2v : 0;
    float v[16];
#pragma unroll
    for (int i = 0; i < 16; i++) {
        float t = d_x2max[(size_t)n * 16 + i];
        v[i] = (t == -INFINITY) ? 0.0f : t;
    }
    float* g = d_gsum + b * 16;
    red_add_v4(g,      make_float4(v[0], v[1], v[2], v[3]));
    red_add_v4(g + 4,  make_float4(v[4], v[5], v[6], v[7]));
    red_add_v4(g + 8,  make_float4(v[8], v[9], v[10], v[11]));
    red_add_v4(g + 12, make_float4(v[12], v[13], v[14], v[15]));
    atomicAdd(&d_gcnt[b], 1);
}

// B=16 MLP head, single block
__global__ void k_mlp(const float* __restrict__ fc1w, const float* __restrict__ fc1b,
                      const float* __restrict__ fc2w, const float* __restrict__ fc2b,
                      float* __restrict__ out) {
    __shared__ float g[BGRAPH * 16];
    __shared__ float hid[BGRAPH * 64];
    int t = threadIdx.x;  // 256 threads
    if (t < BGRAPH * 16) {
        int b = t >> 4;
        int c = d_gcnt[b];
        g[t] = d_gsum[t] / (float)(c > 1 ? c : 1);
    }
    __syncthreads();
    for (int i = t; i < BGRAPH * 64; i += 256) {
        int b = i >> 6, j = i & 63;
        float s = fc1b[j];
#pragma unroll
        for (int k = 0; k < 16; k++) s += g[b * 16 + k] * fc1w[k * 64 + j];
        hid[i] = elu1(s);
    }
    __syncthreads();
    if (t < BGRAPH) {
        float s = fc2b[0];
#pragma unroll
        for (int j = 0; j < 64; j++) s += hid[t * 64 + j] * fc2w[j];
        out[t] = elu1(s);
    }
}

// ---------------- launch ----------------
extern "C" void kernel_launch(void* const* d_in, const int* in_sizes, int n_in,
                              void* d_out, int out_size) {
    const float* x        = (const float*)d_in[0];
    const int*   ei       = (const int*)d_in[1];
    const float* attr     = (const float*)d_in[2];
    const int*   batch    = (const int*)d_in[3];
    const int*   cluster1 = (const int*)d_in[4];
    const int*   cluster2 = (const int*)d_in[5];
    const float* W1       = (const float*)d_in[6];
    const float* root1    = (const float*)d_in[7];
    const float* b1       = (const float*)d_in[8];
    const float* W2       = (const float*)d_in[9];
    const float* root2    = (const float*)d_in[10];
    const float* b2       = (const float*)d_in[11];
    const float* fc1w     = (const float*)d_in[12];
    const float* fc1b     = (const float*)d_in[13];
    const float* fc2w     = (const float*)d_in[14];
    const float* fc2b     = (const float*)d_in[15];
    float* out = (float*)d_out;

    int N  = in_sizes[0] / 2;
    int E  = in_sizes[1] / 2;
    int N1 = in_sizes[5];      // cluster2 has length N1
    int N2 = N1 / 2;

    const int T = 256;
    k_init<<<512, T>>>(N, N1, N2);
    k_xw1<<<(N * NUMK + T - 1) / T, T>>>(x, W1, N);
    k_edge1<<<(E + T - 1) / T, T>>>(ei, attr, E);
    k_node1<<<(N + T - 1) / T, T>>>(x, batch, cluster1, root1, b1, N);
    k_xw2<<<(N1 * NUMK + T - 1) / T, T>>>(W2, N1);
    k_edge2<<<(E + T - 1) / T, T>>>(ei, attr, cluster1, E);
    k_node2<<<(N1 + T - 1) / T, T>>>(cluster2, root2, b2, N1);
    k_final<<<(N2 + T - 1) / T, T>>>(N2);
    k_mlp<<<1, T>>>(fc1w, fc1b, fc2w, fc2b, out);
}

// round 2
// speedup vs baseline: 1.3099x; 1.3099x over previous
#include <cuda_runtime.h>
#include <math.h>

// Problem dims (fixed by the dataset)
#define NMAX   80000
#define N1MAX  40000
#define N2MAX  20000
#define EMAX   1280000
#define NUMK   27
#define BGRAPH 16

// ---------------- scratch (static __device__ — no allocations) ----------------
__device__ float d_xw2[N1MAX * NUMK * 16];   // 69 MB
__device__ float d_agg1[NMAX * 8];
__device__ int   d_cnt1[NMAX];
__device__ float d_x1max[N1MAX * 8];
__device__ int   d_batch1[N1MAX];
__device__ float d_agg2[N1MAX * 16];
__device__ int   d_cnt2[N1MAX];
__device__ float d_x2max[N2MAX * 16];
__device__ int   d_batch2[N2MAX];
__device__ float d_gsum[BGRAPH * 16];
__device__ int   d_gcnt[BGRAPH];
__device__ int   d_src2[EMAX];
__device__ int   d_dst2[EMAX];

// ---------------- helpers ----------------
__device__ __forceinline__ float elu1(float v) {
    return v > 0.0f ? v : (expf(v) - 1.0f);
}

__device__ __forceinline__ void atomicMaxFloat(float* addr, float value) {
    if (value >= 0.0f)
        atomicMax((int*)addr, __float_as_int(value));
    else
        atomicMin((unsigned int*)addr, __float_as_uint(value));
}

__device__ __forceinline__ void red_add_v4(float* p, float4 v) {
    asm volatile("red.global.add.v4.f32 [%0], {%1,%2,%3,%4};"
                 :: "l"(p), "f"(v.x), "f"(v.y), "f"(v.z), "f"(v.w) : "memory");
}

__device__ __forceinline__ float4 f4fma(float b, float4 a, float4 acc) {
    acc.x += b * a.x; acc.y += b * a.y; acc.z += b * a.z; acc.w += b * a.w;
    return acc;
}

// degree-1 open B-spline basis on 3-dim pseudo coords, K=3
__device__ __forceinline__ void basis27(float a0, float a1, float a2,
                                        float* bw, int* kk) {
    float v0 = a0 * 2.0f, v1 = a1 * 2.0f, v2 = a2 * 2.0f;
    int i0 = (int)v0; i0 = i0 < 0 ? 0 : (i0 > 1 ? 1 : i0);
    int i1 = (int)v1; i1 = i1 < 0 ? 0 : (i1 > 1 ? 1 : i1);
    int i2 = (int)v2; i2 = i2 < 0 ? 0 : (i2 > 1 ? 1 : i2);
    float f0 = v0 - (float)i0, f1 = v1 - (float)i1, f2 = v2 - (float)i2;
    float g0 = 1.0f - f0, g1 = 1.0f - f1, g2 = 1.0f - f2;
#pragma unroll
    for (int s = 0; s < 8; s++) {
        int b0 = s & 1, b1 = (s >> 1) & 1, b2 = (s >> 2) & 1;
        float w0 = b0 ? f0 : g0;
        float w1 = b1 ? f1 : g1;
        float w2 = b2 ? f2 : g2;
        bw[s] = w0 * w1 * w2;
        kk[s] = (i0 + b0) + 3 * (i1 + b1) + 9 * (i2 + b2);
    }
}

// ---------------- kernels ----------------

__global__ void k_init(int N, int N1, int N2) {
    int tid = blockIdx.x * blockDim.x + threadIdx.x;
    int stride = gridDim.x * blockDim.x;
    for (int i = tid; i < N * 8; i += stride)  d_agg1[i] = 0.0f;
    for (int i = tid; i < N; i += stride)      d_cnt1[i] = 0;
    for (int i = tid; i < N1 * 8; i += stride) d_x1max[i] = -INFINITY;
    for (int i = tid; i < N1; i += stride)     d_batch1[i] = -0x7fffffff - 1;
    for (int i = tid; i < N1 * 16; i += stride) d_agg2[i] = 0.0f;
    for (int i = tid; i < N1; i += stride)     d_cnt2[i] = 0;
    for (int i = tid; i < N2 * 16; i += stride) d_x2max[i] = -INFINITY;
    for (int i = tid; i < N2; i += stride)     d_batch2[i] = -0x7fffffff - 1;
    for (int i = tid; i < BGRAPH * 16; i += stride) d_gsum[i] = 0.0f;
    for (int i = tid; i < BGRAPH; i += stride) d_gcnt[i] = 0;
}

// per-edge bookkeeping: degree counts + coarse endpoints (coalesced for k_edge2)
__global__ void k_count(const int* __restrict__ ei, const int* __restrict__ cluster1, int E) {
    int e = blockIdx.x * blockDim.x + threadIdx.x;
    if (e >= E) return;
    int src = ei[e];
    int dst = ei[E + e];
    int s2 = __ldg(&cluster1[src]);
    int d2 = __ldg(&cluster1[dst]);
    d_src2[e] = s2;
    d_dst2[e] = d2;
    atomicAdd(&d_cnt1[dst], 1);
    atomicAdd(&d_cnt2[d2], 1);
}

// level-1 edge kernel: W1 in shared, gather only x_src (8B/edge)
// msg = x0 * (sum_s b_s W1[k_s,0,:]) + x1 * (sum_s b_s W1[k_s,1,:])
__global__ void k_edge1(const int* __restrict__ ei, const float* __restrict__ attr,
                        const float* __restrict__ x, const float* __restrict__ W1, int E) {
    __shared__ float4 sW[NUMK * 5];  // stride 5 float4 per k: [uLo, uHi, vLo, vHi, pad]
    int t = threadIdx.x;
    if (t < NUMK * 4) {
        int k = t >> 2, j = t & 3;
        sW[k * 5 + j] = ((const float4*)W1)[t];
    }
    __syncthreads();
    int e = blockIdx.x * blockDim.x + t;
    if (e >= E) return;
    int src = ei[e];
    int dst = ei[E + e];
    float a0 = attr[3 * e], a1 = attr[3 * e + 1], a2 = attr[3 * e + 2];
    float bw[8]; int kk[8];
    basis27(a0, a1, a2, bw, kk);
    float4 uL = make_float4(0, 0, 0, 0), uH = uL, vL = uL, vH = uL;
#pragma unroll
    for (int s = 0; s < 8; s++) {
        float b = bw[s];
        const float4* p = &sW[kk[s] * 5];
        uL = f4fma(b, p[0], uL);
        uH = f4fma(b, p[1], uH);
        vL = f4fma(b, p[2], vL);
        vH = f4fma(b, p[3], vH);
    }
    float2 xv = __ldg((const float2*)(x) + src);   // the only random gather: 8B
    float4 mL, mH;
    mL.x = xv.x * uL.x + xv.y * vL.x; mL.y = xv.x * uL.y + xv.y * vL.y;
    mL.z = xv.x * uL.z + xv.y * vL.z; mL.w = xv.x * uL.w + xv.y * vL.w;
    mH.x = xv.x * uH.x + xv.y * vH.x; mH.y = xv.x * uH.y + xv.y * vH.y;
    mH.z = xv.x * uH.z + xv.y * vH.z; mH.w = xv.x * uH.w + xv.y * vH.w;
    float* out = d_agg1 + (size_t)dst * 8;
    red_add_v4(out, mL);
    red_add_v4(out + 4, mH);
}

// level-1 node kernel: mean + root + bias + ELU, then seg_max pooling scatter
__global__ void k_node1(const float* __restrict__ x, const int* __restrict__ batch,
                        const int* __restrict__ cluster1,
                        const float* __restrict__ root1, const float* __restrict__ b1,
                        int N) {
    int n = blockIdx.x * blockDim.x + threadIdx.x;
    if (n >= N) return;
    int c = d_cnt1[n];
    float inv = 1.0f / (float)(c > 1 ? c : 1);
    float x0 = x[2 * n], x1 = x[2 * n + 1];
    int c1 = cluster1[n];
    int bt = batch[n];
    float* xm = d_x1max + (size_t)c1 * 8;
#pragma unroll
    for (int o = 0; o < 8; o++) {
        float h = d_agg1[(size_t)n * 8 + o] * inv + x0 * root1[o] + x1 * root1[8 + o] + b1[o];
        h = elu1(h);
        atomicMaxFloat(&xm[o], h);
    }
    atomicMax(&d_batch1[c1], bt);
}

// xW2[n1][k][o] = x1_fixed[n1] @ W2[k]   (N1*27 threads, 16 outputs each)
__global__ void k_xw2(const float* __restrict__ W2, int N1) {
    int idx = blockIdx.x * blockDim.x + threadIdx.x;
    if (idx >= N1 * NUMK) return;
    int n = idx / NUMK;
    int k = idx - n * NUMK;
    float xv[8];
#pragma unroll
    for (int c = 0; c < 8; c++) {
        float t = d_x1max[(size_t)n * 8 + c];
        xv[c] = (t == -INFINITY) ? 0.0f : t;   // seg_max empty-cluster fix
    }
    const float* w = W2 + k * 128;
    float r[16];
#pragma unroll
    for (int o = 0; o < 16; o++) r[o] = 0.0f;
#pragma unroll
    for (int c = 0; c < 8; c++) {
        float xc = xv[c];
        const float* wr = w + c * 16;
#pragma unroll
        for (int o = 0; o < 16; o++) r[o] += xc * wr[o];
    }
    float4* out = (float4*)(d_xw2) + (size_t)idx * 4;
    out[0] = make_float4(r[0], r[1], r[2], r[3]);
    out[1] = make_float4(r[4], r[5], r[6], r[7]);
    out[2] = make_float4(r[8], r[9], r[10], r[11]);
    out[3] = make_float4(r[12], r[13], r[14], r[15]);
}

// level-2 edge kernel: 4 lanes per edge, each lane owns 4 output channels.
// Corner row (64B) fetched by 4 lanes as one contiguous LDG.128 group -> 1 line/edge-corner.
__global__ void k_edge2(const float* __restrict__ attr, int E) {
    int t = blockIdx.x * blockDim.x + threadIdx.x;
    int e = t >> 2;          // edge index
    int sub = t & 3;         // channel quartet
    if (e >= E) return;
    int s2 = d_src2[e];
    int d2 = d_dst2[e];
    float a0 = attr[3 * e], a1 = attr[3 * e + 1], a2 = attr[3 * e + 2];
    float bw[8]; int kk[8];
    basis27(a0, a1, a2, bw, kk);
    const float4* base = (const float4*)d_xw2 + (size_t)s2 * (NUMK * 4) + sub;
    float4 w[8];
#pragma unroll
    for (int s = 0; s < 8; s++) w[s] = __ldg(base + kk[s] * 4);
    float4 m = make_float4(0, 0, 0, 0);
#pragma unroll
    for (int s = 0; s < 8; s++) m = f4fma(bw[s], w[s], m);
    red_add_v4(d_agg2 + (size_t)d2 * 16 + sub * 4, m);
}

// level-2 node kernel: mean + root + bias + ELU, then seg_max pooling scatter
__global__ void k_node2(const int* __restrict__ cluster2,
                        const float* __restrict__ root2, const float* __restrict__ b2,
                        int N1) {
    int n = blockIdx.x * blockDim.x + threadIdx.x;
    if (n >= N1) return;
    int c = d_cnt2[n];
    float inv = 1.0f / (float)(c > 1 ? c : 1);
    float xv[8];
#pragma unroll
    for (int i = 0; i < 8; i++) {
        float t = d_x1max[(size_t)n * 8 + i];
        xv[i] = (t == -INFINITY) ? 0.0f : t;
    }
    int c2 = cluster2[n];
    int b1v = d_batch1[n];
    int bt = b1v > 0 ? b1v : 0;
    float* xm = d_x2max + (size_t)c2 * 16;
#pragma unroll
    for (int o = 0; o < 16; o++) {
        float r = 0.0f;
#pragma unroll
        for (int i = 0; i < 8; i++) r += xv[i] * __ldg(&root2[i * 16 + o]);
        float h = d_agg2[(size_t)n * 16 + o] * inv + r + b2[o];
        h = elu1(h);
        atomicMaxFloat(&xm[o], h);
    }
    atomicMax(&d_batch2[c2], bt);
}

// scatter_mean over graphs
__global__ void k_final(int N2) {
    int n = blockIdx.x * blockDim.x + threadIdx.x;
    if (n >= N2) return;
    int b2v = d_batch2[n];
    int b = b2v > 0 ? b2v : 0;
    float v[16];
#pragma unroll
    for (int i = 0; i < 16; i++) {
        float t = d_x2max[(size_t)n * 16 + i];
        v[i] = (t == -INFINITY) ? 0.0f : t;
    }
    float* g = d_gsum + b * 16;
    red_add_v4(g,      make_float4(v[0], v[1], v[2], v[3]));
    red_add_v4(g + 4,  make_float4(v[4], v[5], v[6], v[7]));
    red_add_v4(g + 8,  make_float4(v[8], v[9], v[10], v[11]));
    red_add_v4(g + 12, make_float4(v[12], v[13], v[14], v[15]));
    atomicAdd(&d_gcnt[b], 1);
}

// B=16 MLP head, single block
__global__ void k_mlp(const float* __restrict__ fc1w, const float* __restrict__ fc1b,
                      const float* __restrict__ fc2w, const float* __restrict__ fc2b,
                      float* __restrict__ out) {
    __shared__ float g[BGRAPH * 16];
    __shared__ float hid[BGRAPH * 64];
    int t = threadIdx.x;  // 256 threads
    if (t < BGRAPH * 16) {
        int b = t >> 4;
        int c = d_gcnt[b];
        g[t] = d_gsum[t] / (float)(c > 1 ? c : 1);
    }
    __syncthreads();
    for (int i = t; i < BGRAPH * 64; i += 256) {
        int b = i >> 6, j = i & 63;
        float s = fc1b[j];
#pragma unroll
        for (int k = 0; k < 16; k++) s += g[b * 16 + k] * fc1w[k * 64 + j];
        hid[i] = elu1(s);
    }
    __syncthreads();
    if (t < BGRAPH) {
        float s = fc2b[0];
#pragma unroll
        for (int j = 0; j < 64; j++) s += hid[t * 64 + j] * fc2w[j];
        out[t] = elu1(s);
    }
}

// ---------------- launch ----------------
extern "C" void kernel_launch(void* const* d_in, const int* in_sizes, int n_in,
                              void* d_out, int out_size) {
    const float* x        = (const float*)d_in[0];
    const int*   ei       = (const int*)d_in[1];
    const float* attr     = (const float*)d_in[2];
    const int*   batch    = (const int*)d_in[3];
    const int*   cluster1 = (const int*)d_in[4];
    const int*   cluster2 = (const int*)d_in[5];
    const float* W1       = (const float*)d_in[6];
    const float* root1    = (const float*)d_in[7];
    const float* b1       = (const float*)d_in[8];
    const float* W2       = (const float*)d_in[9];
    const float* root2    = (const float*)d_in[10];
    const float* b2       = (const float*)d_in[11];
    const float* fc1w     = (const float*)d_in[12];
    const float* fc1b     = (const float*)d_in[13];
    const float* fc2w     = (const float*)d_in[14];
    const float* fc2b     = (const float*)d_in[15];
    float* out = (float*)d_out;

    int N  = in_sizes[0] / 2;
    int E  = in_sizes[1] / 2;
    int N1 = in_sizes[5];      // cluster2 has length N1
    int N2 = N1 / 2;

    const int T = 256;
    k_init<<<512, T>>>(N, N1, N2);
    k_count<<<(E + T - 1) / T, T>>>(ei, cluster1, E);
    k_edge1<<<(E + T - 1) / T, T>>>(ei, attr, x, W1, E);
    k_node1<<<(N + T - 1) / T, T>>>(x, batch, cluster1, root1, b1, N);
    k_xw2<<<(N1 * NUMK + T - 1) / T, T>>>(W2, N1);
    k_edge2<<<(4 * E + T - 1) / T, T>>>(attr, E);
    k_node2<<<(N1 + T - 1) / T, T>>>(cluster2, root2, b2, N1);
    k_final<<<(N2 + T - 1) / T, T>>>(N2);
    k_mlp<<<1, T>>>(fc1w, fc1b, fc2w, fc2b, out);
}

// round 3
// speedup vs baseline: 1.3658x; 1.0427x over previous
#include <cuda_runtime.h>
#include <cuda_fp16.h>
#include <math.h>

// Problem dims (fixed by the dataset)
#define NMAX   80000
#define N1MAX  40000
#define N2MAX  20000
#define EMAX   1280000
#define NUMK   27
#define BGRAPH 16

// ---------------- scratch (static __device__ — no allocations) ----------------
// fp16 xW2 table, padded: 32 corner-slots (27 used) x 16 halves = 512 halves = 1024B per node
__device__ __align__(16) __half d_xw2h[(size_t)N1MAX * 512];   // 41 MB
__device__ float d_agg1[NMAX * 8];
__device__ int   d_cnt1[NMAX];
__device__ float d_x1max[N1MAX * 8];
__device__ int   d_batch1[N1MAX];
__device__ float d_agg2[N1MAX * 16];
__device__ int   d_cnt2[N1MAX];
__device__ float d_x2max[N2MAX * 16];
__device__ int   d_batch2[N2MAX];
__device__ float d_gsum[BGRAPH * 16];
__device__ int   d_gcnt[BGRAPH];
__device__ int   d_src2[EMAX];
__device__ int   d_dst2[EMAX];

// ---------------- helpers ----------------
__device__ __forceinline__ float elu1(float v) {
    return v > 0.0f ? v : (expf(v) - 1.0f);
}

__device__ __forceinline__ void atomicMaxFloat(float* addr, float value) {
    if (value >= 0.0f)
        atomicMax((int*)addr, __float_as_int(value));
    else
        atomicMin((unsigned int*)addr, __float_as_uint(value));
}

__device__ __forceinline__ void red_add_v4(float* p, float4 v) {
    asm volatile("red.global.add.v4.f32 [%0], {%1,%2,%3,%4};"
                 :: "l"(p), "f"(v.x), "f"(v.y), "f"(v.z), "f"(v.w) : "memory");
}

__device__ __forceinline__ float4 f4fma(float b, float4 a, float4 acc) {
    acc.x += b * a.x; acc.y += b * a.y; acc.z += b * a.z; acc.w += b * a.w;
    return acc;
}

// degree-1 open B-spline basis on 3-dim pseudo coords, K=3
__device__ __forceinline__ void basis27(float a0, float a1, float a2,
                                        float* bw, int* kk) {
    float v0 = a0 * 2.0f, v1 = a1 * 2.0f, v2 = a2 * 2.0f;
    int i0 = (int)v0; i0 = i0 < 0 ? 0 : (i0 > 1 ? 1 : i0);
    int i1 = (int)v1; i1 = i1 < 0 ? 0 : (i1 > 1 ? 1 : i1);
    int i2 = (int)v2; i2 = i2 < 0 ? 0 : (i2 > 1 ? 1 : i2);
    float f0 = v0 - (float)i0, f1 = v1 - (float)i1, f2 = v2 - (float)i2;
    float g0 = 1.0f - f0, g1 = 1.0f - f1, g2 = 1.0f - f2;
#pragma unroll
    for (int s = 0; s < 8; s++) {
        int b0 = s & 1, b1 = (s >> 1) & 1, b2 = (s >> 2) & 1;
        float w0 = b0 ? f0 : g0;
        float w1 = b1 ? f1 : g1;
        float w2 = b2 ? f2 : g2;
        bw[s] = w0 * w1 * w2;
        kk[s] = (i0 + b0) + 3 * (i1 + b1) + 9 * (i2 + b2);
    }
}

// ---------------- kernels ----------------

__global__ void k_init(int N, int N1, int N2) {
    int tid = blockIdx.x * blockDim.x + threadIdx.x;
    int stride = gridDim.x * blockDim.x;
    for (int i = tid; i < N * 8; i += stride)  d_agg1[i] = 0.0f;
    for (int i = tid; i < N; i += stride)      d_cnt1[i] = 0;
    for (int i = tid; i < N1 * 8; i += stride) d_x1max[i] = -INFINITY;
    for (int i = tid; i < N1; i += stride)     d_batch1[i] = -0x7fffffff - 1;
    for (int i = tid; i < N1 * 16; i += stride) d_agg2[i] = 0.0f;
    for (int i = tid; i < N1; i += stride)     d_cnt2[i] = 0;
    for (int i = tid; i < N2 * 16; i += stride) d_x2max[i] = -INFINITY;
    for (int i = tid; i < N2; i += stride)     d_batch2[i] = -0x7fffffff - 1;
    for (int i = tid; i < BGRAPH * 16; i += stride) d_gsum[i] = 0.0f;
    for (int i = tid; i < BGRAPH; i += stride) d_gcnt[i] = 0;
}

// level-1 edge kernel + bookkeeping fused:
// msg = x0 * (sum_s b_s W1[k_s,0,:]) + x1 * (sum_s b_s W1[k_s,1,:])
// also: cnt1[dst]++, cnt2[d2]++, write coarse endpoints for k_edge2.
__global__ void __launch_bounds__(256) k_edge1(
        const int* __restrict__ ei, const float* __restrict__ attr,
        const float* __restrict__ x, const float* __restrict__ W1,
        const int* __restrict__ cluster1, int E) {
    __shared__ float4 sW[NUMK * 5];  // stride 5 float4 per k: [uLo, uHi, vLo, vHi, pad]
    int t = threadIdx.x;
    if (t < NUMK * 4) {
        int k = t >> 2, j = t & 3;
        sW[k * 5 + j] = ((const float4*)W1)[t];
    }
    __syncthreads();
    int e = blockIdx.x * blockDim.x + t;
    if (e >= E) return;
    int src = ei[e];
    int dst = ei[E + e];
    int s2 = __ldg(&cluster1[src]);
    int d2 = __ldg(&cluster1[dst]);
    d_src2[e] = s2;
    d_dst2[e] = d2;
    atomicAdd(&d_cnt1[dst], 1);
    atomicAdd(&d_cnt2[d2], 1);
    float a0 = attr[3 * e], a1 = attr[3 * e + 1], a2 = attr[3 * e + 2];
    float bw[8]; int kk[8];
    basis27(a0, a1, a2, bw, kk);
    float4 uL = make_float4(0, 0, 0, 0), uH = uL, vL = uL, vH = uL;
#pragma unroll
    for (int s = 0; s < 8; s++) {
        float b = bw[s];
        const float4* p = &sW[kk[s] * 5];
        uL = f4fma(b, p[0], uL);
        uH = f4fma(b, p[1], uH);
        vL = f4fma(b, p[2], vL);
        vH = f4fma(b, p[3], vH);
    }
    float2 xv = __ldg((const float2*)(x) + src);   // the only random gather: 8B
    float4 mL, mH;
    mL.x = xv.x * uL.x + xv.y * vL.x; mL.y = xv.x * uL.y + xv.y * vL.y;
    mL.z = xv.x * uL.z + xv.y * vL.z; mL.w = xv.x * uL.w + xv.y * vL.w;
    mH.x = xv.x * uH.x + xv.y * vH.x; mH.y = xv.x * uH.y + xv.y * vH.y;
    mH.z = xv.x * uH.z + xv.y * vH.z; mH.w = xv.x * uH.w + xv.y * vH.w;
    float* out = d_agg1 + (size_t)dst * 8;
    red_add_v4(out, mL);
    red_add_v4(out + 4, mH);
}

// level-1 node kernel: mean + root + bias + ELU, then seg_max pooling scatter
__global__ void k_node1(const float* __restrict__ x, const int* __restrict__ batch,
                        const int* __restrict__ cluster1,
                        const float* __restrict__ root1, const float* __restrict__ b1,
                        int N) {
    int n = blockIdx.x * blockDim.x + threadIdx.x;
    if (n >= N) return;
    int c = d_cnt1[n];
    float inv = 1.0f / (float)(c > 1 ? c : 1);
    float x0 = x[2 * n], x1 = x[2 * n + 1];
    int c1 = cluster1[n];
    int bt = batch[n];
    float* xm = d_x1max + (size_t)c1 * 8;
#pragma unroll
    for (int o = 0; o < 8; o++) {
        float h = d_agg1[(size_t)n * 8 + o] * inv + x0 * root1[o] + x1 * root1[8 + o] + b1[o];
        h = elu1(h);
        atomicMaxFloat(&xm[o], h);
    }
    atomicMax(&d_batch1[c1], bt);
}

// xW2 table in fp16, padded rows: [n][32 corner slots][16 half]
__global__ void k_xw2(const float* __restrict__ W2, int N1) {
    int idx = blockIdx.x * blockDim.x + threadIdx.x;
    if (idx >= N1 * NUMK) return;
    int n = idx / NUMK;
    int k = idx - n * NUMK;
    float xv[8];
#pragma unroll
    for (int c = 0; c < 8; c++) {
        float t = d_x1max[(size_t)n * 8 + c];
        xv[c] = (t == -INFINITY) ? 0.0f : t;   // seg_max empty-cluster fix
    }
    const float* w = W2 + k * 128;
    float r[16];
#pragma unroll
    for (int o = 0; o < 16; o++) r[o] = 0.0f;
#pragma unroll
    for (int c = 0; c < 8; c++) {
        float xc = xv[c];
        const float* wr = w + c * 16;
#pragma unroll
        for (int o = 0; o < 16; o++) r[o] += xc * wr[o];
    }
    __half2 h[8];
#pragma unroll
    for (int i = 0; i < 8; i++) h[i] = __floats2half2_rn(r[2 * i], r[2 * i + 1]);
    uint4* out = (uint4*)(d_xw2h + (size_t)n * 512 + k * 16);
    uint4 q0, q1;
    q0.x = *(unsigned*)&h[0]; q0.y = *(unsigned*)&h[1];
    q0.z = *(unsigned*)&h[2]; q0.w = *(unsigned*)&h[3];
    q1.x = *(unsigned*)&h[4]; q1.y = *(unsigned*)&h[5];
    q1.z = *(unsigned*)&h[6]; q1.w = *(unsigned*)&h[7];
    out[0] = q0;
    out[1] = q1;
}

// level-2 edge kernel: 2 lanes per edge, each lane owns 8 output channels.
// Each corner read = one 16B load per lane; lane pair covers one fully-used 32B sector.
__global__ void __launch_bounds__(256) k_edge2(const float* __restrict__ attr, int E) {
    int t = blockIdx.x * blockDim.x + threadIdx.x;
    int e = t >> 1;          // edge index
    int sub = t & 1;         // channel octet
    if (e >= E) return;
    int s2 = d_src2[e];
    int d2 = d_dst2[e];
    float a0 = attr[3 * e], a1 = attr[3 * e + 1], a2 = attr[3 * e + 2];
    float bw[8]; int kk[8];
    basis27(a0, a1, a2, bw, kk);
    const uint4* base = (const uint4*)(d_xw2h + (size_t)s2 * 512) + sub;
    uint4 q[8];
#pragma unroll
    for (int s = 0; s < 8; s++) q[s] = __ldg(base + kk[s] * 2);
    float m[8];
#pragma unroll
    for (int i = 0; i < 8; i++) m[i] = 0.0f;
#pragma unroll
    for (int s = 0; s < 8; s++) {
        float b = bw[s];
        float2 f0 = __half22float2(*(__half2*)&q[s].x);
        float2 f1 = __half22float2(*(__half2*)&q[s].y);
        float2 f2 = __half22float2(*(__half2*)&q[s].z);
        float2 f3 = __half22float2(*(__half2*)&q[s].w);
        m[0] += b * f0.x; m[1] += b * f0.y;
        m[2] += b * f1.x; m[3] += b * f1.y;
        m[4] += b * f2.x; m[5] += b * f2.y;
        m[6] += b * f3.x; m[7] += b * f3.y;
    }
    float* out = d_agg2 + (size_t)d2 * 16 + sub * 8;
    red_add_v4(out,     make_float4(m[0], m[1], m[2], m[3]));
    red_add_v4(out + 4, make_float4(m[4], m[5], m[6], m[7]));
}

// level-2 node kernel: mean + root + bias + ELU, then seg_max pooling scatter
__global__ void k_node2(const int* __restrict__ cluster2,
                        const float* __restrict__ root2, const float* __restrict__ b2,
                        int N1) {
    int n = blockIdx.x * blockDim.x + threadIdx.x;
    if (n >= N1) return;
    int c = d_cnt2[n];
    float inv = 1.0f / (float)(c > 1 ? c : 1);
    float xv[8];
#pragma unroll
    for (int i = 0; i < 8; i++) {
        float t = d_x1max[(size_t)n * 8 + i];
        xv[i] = (t == -INFINITY) ? 0.0f : t;
    }
    int c2 = cluster2[n];
    int b1v = d_batch1[n];
    int bt = b1v > 0 ? b1v : 0;
    float* xm = d_x2max + (size_t)c2 * 16;
#pragma unroll
    for (int o = 0; o < 16; o++) {
        float r = 0.0f;
#pragma unroll
        for (int i = 0; i < 8; i++) r += xv[i] * __ldg(&root2[i * 16 + o]);
        float h = d_agg2[(size_t)n * 16 + o] * inv + r + b2[o];
        h = elu1(h);
        atomicMaxFloat(&xm[o], h);
    }
    atomicMax(&d_batch2[c2], bt);
}

// scatter_mean over graphs
__global__ void k_final(int N2) {
    int n = blockIdx.x * blockDim.x + threadIdx.x;
    if (n >= N2) return;
    int b2v = d_batch2[n];
    int b = b2v > 0 ? b2v : 0;
    float v[16];
#pragma unroll
    for (int i = 0; i < 16; i++) {
        float t = d_x2max[(size_t)n * 16 + i];
        v[i] = (t == -INFINITY) ? 0.0f : t;
    }
    float* g = d_gsum + b * 16;
    red_add_v4(g,      make_float4(v[0], v[1], v[2], v[3]));
    red_add_v4(g + 4,  make_float4(v[4], v[5], v[6], v[7]));
    red_add_v4(g + 8,  make_float4(v[8], v[9], v[10], v[11]));
    red_add_v4(g + 12, make_float4(v[12], v[13], v[14], v[15]));
    atomicAdd(&d_gcnt[b], 1);
}

// B=16 MLP head, single block
__global__ void k_mlp(const float* __restrict__ fc1w, const float* __restrict__ fc1b,
                      const float* __restrict__ fc2w, const float* __restrict__ fc2b,
                      float* __restrict__ out) {
    __shared__ float g[BGRAPH * 16];
    __shared__ float hid[BGRAPH * 64];
    int t = threadIdx.x;  // 256 threads
    if (t < BGRAPH * 16) {
        int b = t >> 4;
        int c = d_gcnt[b];
        g[t] = d_gsum[t] / (float)(c > 1 ? c : 1);
    }
    __syncthreads();
    for (int i = t; i < BGRAPH * 64; i += 256) {
        int b = i >> 6, j = i & 63;
        float s = fc1b[j];
#pragma unroll
        for (int k = 0; k < 16; k++) s += g[b * 16 + k] * fc1w[k * 64 + j];
        hid[i] = elu1(s);
    }
    __syncthreads();
    if (t < BGRAPH) {
        float s = fc2b[0];
#pragma unroll
        for (int j = 0; j < 64; j++) s += hid[t * 64 + j] * fc2w[j];
        out[t] = elu1(s);
    }
}

// ---------------- launch ----------------
extern "C" void kernel_launch(void* const* d_in, const int* in_sizes, int n_in,
                              void* d_out, int out_size) {
    const float* x        = (const float*)d_in[0];
    const int*   ei       = (const int*)d_in[1];
    const float* attr     = (const float*)d_in[2];
    const int*   batch    = (const int*)d_in[3];
    const int*   cluster1 = (const int*)d_in[4];
    const int*   cluster2 = (const int*)d_in[5];
    const float* W1       = (const float*)d_in[6];
    const float* root1    = (const float*)d_in[7];
    const float* b1       = (const float*)d_in[8];
    const float* W2       = (const float*)d_in[9];
    const float* root2    = (const float*)d_in[10];
    const float* b2       = (const float*)d_in[11];
    const float* fc1w     = (const float*)d_in[12];
    const float* fc1b     = (const float*)d_in[13];
    const float* fc2w     = (const float*)d_in[14];
    const float* fc2b     = (const float*)d_in[15];
    float* out = (float*)d_out;

    int N  = in_sizes[0] / 2;
    int E  = in_sizes[1] / 2;
    int N1 = in_sizes[5];      // cluster2 has length N1
    int N2 = N1 / 2;

    const int T = 256;
    k_init<<<512, T>>>(N, N1, N2);
    k_edge1<<<(E + T - 1) / T, T>>>(ei, attr, x, W1, cluster1, E);
    k_node1<<<(N + T - 1) / T, T>>>(x, batch, cluster1, root1, b1, N);
    k_xw2<<<(N1 * NUMK + T - 1) / T, T>>>(W2, N1);
    k_edge2<<<(2 * E + T - 1) / T, T>>>(attr, E);
    k_node2<<<(N1 + T - 1) / T, T>>>(cluster2, root2, b2, N1);
    k_final<<<(N2 + T - 1) / T, T>>>(N2);
    k_mlp<<<1, T>>>(fc1w, fc1b, fc2w, fc2b, out);
}

// round 5
// speedup vs baseline: 3.9091x; 2.8621x over previous
#include <cuda_runtime.h>
#include <cuda_fp16.h>
#include <math.h>

// Problem dims (fixed by the dataset)
#define NMAX   80000
#define N1MAX  40000
#define N2MAX  20000
#define EMAX   1280000
#define NUMK   27
#define BGRAPH 16

// ---------------- scratch (static __device__ — no allocations) ----------------
// fp16 xW2 table, padded: 32 corner-slots (27 used) x 16 halves = 512 halves = 1024B per node
__device__ __align__(16) __half d_xw2h[(size_t)N1MAX * 512];   // 41 MB
__device__ float d_agg1[NMAX * 8];
__device__ int   d_cnt1[NMAX];
__device__ float d_x1max[N1MAX * 8];
__device__ int   d_batch1[N1MAX];
__device__ float d_agg2[N1MAX * 16];
__device__ int   d_cnt2[N1MAX];
__device__ float d_x2max[N2MAX * 16];
__device__ int   d_batch2[N2MAX];
__device__ float d_gsum[BGRAPH * 16];
__device__ int   d_gcnt[BGRAPH];
__device__ int   d_src2[EMAX];
__device__ int   d_dst2[EMAX];

// ---------------- helpers ----------------
__device__ __forceinline__ float elu1(float v) {
    return v > 0.0f ? v : (expf(v) - 1.0f);
}

__device__ __forceinline__ void atomicMaxFloat(float* addr, float value) {
    if (value >= 0.0f)
        atomicMax((int*)addr, __float_as_int(value));
    else
        atomicMin((unsigned int*)addr, __float_as_uint(value));
}

__device__ __forceinline__ void red_add_v4(float* p, float4 v) {
    asm volatile("red.global.add.v4.f32 [%0], {%1,%2,%3,%4};"
                 :: "l"(p), "f"(v.x), "f"(v.y), "f"(v.z), "f"(v.w) : "memory");
}

__device__ __forceinline__ float4 f4fma(float b, float4 a, float4 acc) {
    acc.x += b * a.x; acc.y += b * a.y; acc.z += b * a.z; acc.w += b * a.w;
    return acc;
}

// degree-1 open B-spline basis on 3-dim pseudo coords, K=3
__device__ __forceinline__ void basis27(float a0, float a1, float a2,
                                        float* bw, int* kk) {
    float v0 = a0 * 2.0f, v1 = a1 * 2.0f, v2 = a2 * 2.0f;
    int i0 = (int)v0; i0 = i0 < 0 ? 0 : (i0 > 1 ? 1 : i0);
    int i1 = (int)v1; i1 = i1 < 0 ? 0 : (i1 > 1 ? 1 : i1);
    int i2 = (int)v2; i2 = i2 < 0 ? 0 : (i2 > 1 ? 1 : i2);
    float f0 = v0 - (float)i0, f1 = v1 - (float)i1, f2 = v2 - (float)i2;
    float g0 = 1.0f - f0, g1 = 1.0f - f1, g2 = 1.0f - f2;
#pragma unroll
    for (int s = 0; s < 8; s++) {
        int b0 = s & 1, b1 = (s >> 1) & 1, b2 = (s >> 2) & 1;
        float w0 = b0 ? f0 : g0;
        float w1 = b1 ? f1 : g1;
        float w2 = b2 ? f2 : g2;
        bw[s] = w0 * w1 * w2;
        kk[s] = (i0 + b0) + 3 * (i1 + b1) + 9 * (i2 + b2);
    }
}

// ---------------- kernels ----------------

__global__ void k_init(int N, int N1, int N2) {
    int tid = blockIdx.x * blockDim.x + threadIdx.x;
    int stride = gridDim.x * blockDim.x;
    for (int i = tid; i < N * 8; i += stride)  d_agg1[i] = 0.0f;
    for (int i = tid; i < N; i += stride)      d_cnt1[i] = 0;
    for (int i = tid; i < N1 * 8; i += stride) d_x1max[i] = -INFINITY;
    for (int i = tid; i < N1; i += stride)     d_batch1[i] = -0x7fffffff - 1;
    for (int i = tid; i < N1 * 16; i += stride) d_agg2[i] = 0.0f;
    for (int i = tid; i < N1; i += stride)     d_cnt2[i] = 0;
    for (int i = tid; i < N2 * 16; i += stride) d_x2max[i] = -INFINITY;
    for (int i = tid; i < N2; i += stride)     d_batch2[i] = -0x7fffffff - 1;
    for (int i = tid; i < BGRAPH * 16; i += stride) d_gsum[i] = 0.0f;
    for (int i = tid; i < BGRAPH; i += stride) d_gcnt[i] = 0;
}

// level-1 edge kernel + bookkeeping fused:
// msg = x0 * (sum_s b_s W1[k_s,0,:]) + x1 * (sum_s b_s W1[k_s,1,:])
// also: cnt1[dst]++, cnt2[d2]++, write coarse endpoints for k_edge2.
__global__ void __launch_bounds__(256) k_edge1(
        const int* __restrict__ ei, const float* __restrict__ attr,
        const float* __restrict__ x, const float* __restrict__ W1,
        const int* __restrict__ cluster1, int E) {
    __shared__ float4 sW[NUMK * 5];  // stride 5 float4 per k: [uLo, uHi, vLo, vHi, pad]
    int t = threadIdx.x;
    if (t < NUMK * 4) {
        int k = t >> 2, j = t & 3;
        sW[k * 5 + j] = ((const float4*)W1)[t];
    }
    __syncthreads();
    int e = blockIdx.x * blockDim.x + t;
    if (e >= E) return;
    int src = ei[e];
    int dst = ei[E + e];
    int s2 = __ldg(&cluster1[src]);
    int d2 = __ldg(&cluster1[dst]);
    d_src2[e] = s2;
    d_dst2[e] = d2;
    atomicAdd(&d_cnt1[dst], 1);
    atomicAdd(&d_cnt2[d2], 1);
    float a0 = attr[3 * e], a1 = attr[3 * e + 1], a2 = attr[3 * e + 2];
    float bw[8]; int kk[8];
    basis27(a0, a1, a2, bw, kk);
    float4 uL = make_float4(0, 0, 0, 0), uH = uL, vL = uL, vH = uL;
#pragma unroll
    for (int s = 0; s < 8; s++) {
        float b = bw[s];
        const float4* p = &sW[kk[s] * 5];
        uL = f4fma(b, p[0], uL);
        uH = f4fma(b, p[1], uH);
        vL = f4fma(b, p[2], vL);
        vH = f4fma(b, p[3], vH);
    }
    float2 xv = __ldg((const float2*)(x) + src);   // the only random gather: 8B
    float4 mL, mH;
    mL.x = xv.x * uL.x + xv.y * vL.x; mL.y = xv.x * uL.y + xv.y * vL.y;
    mL.z = xv.x * uL.z + xv.y * vL.z; mL.w = xv.x * uL.w + xv.y * vL.w;
    mH.x = xv.x * uH.x + xv.y * vH.x; mH.y = xv.x * uH.y + xv.y * vH.y;
    mH.z = xv.x * uH.z + xv.y * vH.z; mH.w = xv.x * uH.w + xv.y * vH.w;
    float* out = d_agg1 + (size_t)dst * 8;
    red_add_v4(out, mL);
    red_add_v4(out + 4, mH);
}

// level-1 node kernel: mean + root + bias + ELU, then seg_max pooling scatter
__global__ void k_node1(const float* __restrict__ x, const int* __restrict__ batch,
                        const int* __restrict__ cluster1,
                        const float* __restrict__ root1, const float* __restrict__ b1,
                        int N) {
    int n = blockIdx.x * blockDim.x + threadIdx.x;
    if (n >= N) return;
    int c = d_cnt1[n];
    float inv = 1.0f / (float)(c > 1 ? c : 1);
    float x0 = x[2 * n], x1 = x[2 * n + 1];
    int c1 = cluster1[n];
    int bt = batch[n];
    float* xm = d_x1max + (size_t)c1 * 8;
#pragma unroll
    for (int o = 0; o < 8; o++) {
        float h = d_agg1[(size_t)n * 8 + o] * inv + x0 * root1[o] + x1 * root1[8 + o] + b1[o];
        h = elu1(h);
        atomicMaxFloat(&xm[o], h);
    }
    atomicMax(&d_batch1[c1], bt);
}

// xW2 table in fp16, padded rows: [n][32 corner slots][16 half]
// Lane axis = output channel o (16 lanes per node, 2 nodes per warp).
// W2 staged in shared; LDS are conflict-free (consecutive per lane, broadcast across halves).
__global__ void __launch_bounds__(128) k_xw2(const float* __restrict__ W2, int N1) {
    __shared__ float sW[NUMK * 128];   // 13.8 KB: [k][c][o]
    int t = threadIdx.x;
    for (int i = t; i < NUMK * 128; i += 128) sW[i] = W2[i];
    __syncthreads();
    int gwarp = (blockIdx.x * 128 + t) >> 5;
    int lane  = t & 31;
    int node  = gwarp * 2 + (lane >> 4);
    int o     = lane & 15;
    if (node >= N1) return;
    const float* xm = d_x1max + (size_t)node * 8;
    float xv[8];
#pragma unroll
    for (int c = 0; c < 8; c++) {
        float v = xm[c];
        xv[c] = (v == -INFINITY) ? 0.0f : v;   // seg_max empty-cluster fix
    }
    __half* outp = d_xw2h + (size_t)node * 512 + o;
#pragma unroll
    for (int k = 0; k < NUMK; k++) {
        const float* w = sW + k * 128 + o;
        float r = 0.0f;
#pragma unroll
        for (int c = 0; c < 8; c++) r += xv[c] * w[c * 16];
        outp[k * 16] = __float2half_rn(r);
    }
}

// level-2 edge kernel: 2 lanes per edge, each lane owns 8 output channels.
// Each corner read = one 16B load per lane; lane pair covers one fully-used 32B sector.
__global__ void __launch_bounds__(256) k_edge2(const float* __restrict__ attr, int E) {
    int t = blockIdx.x * blockDim.x + threadIdx.x;
    int e = t >> 1;          // edge index
    int sub = t & 1;         // channel octet
    if (e >= E) return;
    int s2 = d_src2[e];
    int d2 = d_dst2[e];
    float a0 = attr[3 * e], a1 = attr[3 * e + 1], a2 = attr[3 * e + 2];
    float bw[8]; int kk[8];
    basis27(a0, a1, a2, bw, kk);
    const uint4* base = (const uint4*)(d_xw2h + (size_t)s2 * 512) + sub;
    uint4 q[8];
#pragma unroll
    for (int s = 0; s < 8; s++) q[s] = __ldg(base + kk[s] * 2);
    float m[8];
#pragma unroll
    for (int i = 0; i < 8; i++) m[i] = 0.0f;
#pragma unroll
    for (int s = 0; s < 8; s++) {
        float b = bw[s];
        float2 f0 = __half22float2(*(__half2*)&q[s].x);
        float2 f1 = __half22float2(*(__half2*)&q[s].y);
        float2 f2 = __half22float2(*(__half2*)&q[s].z);
        float2 f3 = __half22float2(*(__half2*)&q[s].w);
        m[0] += b * f0.x; m[1] += b * f0.y;
        m[2] += b * f1.x; m[3] += b * f1.y;
        m[4] += b * f2.x; m[5] += b * f2.y;
        m[6] += b * f3.x; m[7] += b * f3.y;
    }
    float* out = d_agg2 + (size_t)d2 * 16 + sub * 8;
    red_add_v4(out,     make_float4(m[0], m[1], m[2], m[3]));
    red_add_v4(out + 4, make_float4(m[4], m[5], m[6], m[7]));
}

// level-2 node kernel: mean + root + bias + ELU, then seg_max pooling scatter
__global__ void k_node2(const int* __restrict__ cluster2,
                        const float* __restrict__ root2, const float* __restrict__ b2,
                        int N1) {
    int n = blockIdx.x * blockDim.x + threadIdx.x;
    if (n >= N1) return;
    int c = d_cnt2[n];
    float inv = 1.0f / (float)(c > 1 ? c : 1);
    float xv[8];
#pragma unroll
    for (int i = 0; i < 8; i++) {
        float t = d_x1max[(size_t)n * 8 + i];
        xv[i] = (t == -INFINITY) ? 0.0f : t;
    }
    int c2 = cluster2[n];
    int b1v = d_batch1[n];
    int bt = b1v > 0 ? b1v : 0;
    float* xm = d_x2max + (size_t)c2 * 16;
#pragma unroll
    for (int o = 0; o < 16; o++) {
        float r = 0.0f;
#pragma unroll
        for (int i = 0; i < 8; i++) r += xv[i] * __ldg(&root2[i * 16 + o]);
        float h = d_agg2[(size_t)n * 16 + o] * inv + r + b2[o];
        h = elu1(h);
        atomicMaxFloat(&xm[o], h);
    }
    atomicMax(&d_batch2[c2], bt);
}

// scatter_mean over graphs
__global__ void k_final(int N2) {
    int n = blockIdx.x * blockDim.x + threadIdx.x;
    if (n >= N2) return;
    int b2v = d_batch2[n];
    int b = b2v > 0 ? b2v : 0;
    float v[16];
#pragma unroll
    for (int i = 0; i < 16; i++) {
        float t = d_x2max[(size_t)n * 16 + i];
        v[i] = (t == -INFINITY) ? 0.0f : t;
    }
    float* g = d_gsum + b * 16;
    red_add_v4(g,      make_float4(v[0], v[1], v[2], v[3]));
    red_add_v4(g + 4,  make_float4(v[4], v[5], v[6], v[7]));
    red_add_v4(g + 8,  make_float4(v[8], v[9], v[10], v[11]));
    red_add_v4(g + 12, make_float4(v[12], v[13], v[14], v[15]));
    atomicAdd(&d_gcnt[b], 1);
}

// B=16 MLP head, single block
__global__ void k_mlp(const float* __restrict__ fc1w, const float* __restrict__ fc1b,
                      const float* __restrict__ fc2w, const float* __restrict__ fc2b,
                      float* __restrict__ out) {
    __shared__ float g[BGRAPH * 16];
    __shared__ float hid[BGRAPH * 64];
    int t = threadIdx.x;  // 256 threads
    if (t < BGRAPH * 16) {
        int b = t >> 4;
        int c = d_gcnt[b];
        g[t] = d_gsum[t] / (float)(c > 1 ? c : 1);
    }
    __syncthreads();
    for (int i = t; i < BGRAPH * 64; i += 256) {
        int b = i >> 6, j = i & 63;
        float s = fc1b[j];
#pragma unroll
        for (int k = 0; k < 16; k++) s += g[b * 16 + k] * fc1w[k * 64 + j];
        hid[i] = elu1(s);
    }
    __syncthreads();
    if (t < BGRAPH) {
        float s = fc2b[0];
#pragma unroll
        for (int j = 0; j < 64; j++) s += hid[t * 64 + j] * fc2w[j];
        out[t] = elu1(s);
    }
}

// ---------------- launch ----------------
extern "C" void kernel_launch(void* const* d_in, const int* in_sizes, int n_in,
                              void* d_out, int out_size) {
    const float* x        = (const float*)d_in[0];
    const int*   ei       = (const int*)d_in[1];
    const float* attr     = (const float*)d_in[2];
    const int*   batch    = (const int*)d_in[3];
    const int*   cluster1 = (const int*)d_in[4];
    const int*   cluster2 = (const int*)d_in[5];
    const float* W1       = (const float*)d_in[6];
    const float* root1    = (const float*)d_in[7];
    const float* b1       = (const float*)d_in[8];
    const float* W2       = (const float*)d_in[9];
    const float* root2    = (const float*)d_in[10];
    const float* b2       = (const float*)d_in[11];
    const float* fc1w     = (const float*)d_in[12];
    const float* fc1b     = (const float*)d_in[13];
    const float* fc2w     = (const float*)d_in[14];
    const float* fc2b     = (const float*)d_in[15];
    float* out = (float*)d_out;

    int N  = in_sizes[0] / 2;
    int E  = in_sizes[1] / 2;
    int N1 = in_sizes[5];      // cluster2 has length N1
    int N2 = N1 / 2;

    const int T = 256;
    k_init<<<512, T>>>(N, N1, N2);
    k_edge1<<<(E + T - 1) / T, T>>>(ei, attr, x, W1, cluster1, E);
    k_node1<<<(N + T - 1) / T, T>>>(x, batch, cluster1, root1, b1, N);
    {
        int warps = (N1 + 1) / 2;                 // 2 nodes per warp
        int blocks = (warps * 32 + 127) / 128;
        k_xw2<<<blocks, 128>>>(W2, N1);
    }
    k_edge2<<<(2 * E + T - 1) / T, T>>>(attr, E);
    k_node2<<<(N1 + T - 1) / T, T>>>(cluster2, root2, b2, N1);
    k_final<<<(N2 + T - 1) / T, T>>>(N2);
    k_mlp<<<1, T>>>(fc1w, fc1b, fc2w, fc2b, out);
}